// round 17
// baseline (speedup 1.0000x reference)
#include <cuda_runtime.h>

#define Bn 8
#define Hn 512
#define Wn 512
#define HW (Hn*Wn)
#define NPIX (Bn*HW)
#define WPR 16                 // 32-px words per row
#define PW (NPIX/32)           // words per bit-plane = 65536
#define TR 16
#define HALO 7
#define RT (TR+2*HALO)         // 30 tile rows
#define ITEMS (RT*WPR)         // 480
#define NTH 512
#define NBLK (Bn*(Hn/TR))      // 256 sim blocks total
#define CBLK ((NPIX/4)/256)    // 2048 compress blocks total

// Bit-planes: 0-3 elem bits, 4-6 density bits, 7 grav, 8 fall
__device__ unsigned int g_bp[9 * PW];

__host__ __device__ constexpr unsigned long long make_den_lut() {
    constexpr int d[16] = {1,4,3,2,0,4,4,0,4,3,3,2,3,4,0,0};
    unsigned long long v = 0;
    for (int i = 0; i < 16; i++) v |= (unsigned long long)d[i] << (3*i);
    return v;
}
constexpr unsigned long long DEN_LUT = make_den_lut();
#define GRV_LUT 0x1E9Du

__device__ __forceinline__ unsigned eq_elem4(
    unsigned p0, unsigned p1, unsigned p2, unsigned p3, int E)
{
    unsigned b0 = (E & 1) ? p0 : ~p0;
    unsigned b1 = (E & 2) ? p1 : ~p1;
    unsigned b2 = (E & 4) ? p2 : ~p2;
    unsigned b3 = (E & 8) ? p3 : ~p3;
    return b0 & b1 & b2 & b3;
}

// ---------------------------------------------------------------------------
// Compress (R8/R16 body): warp = 128 consecutive pixels, select chain +
// ballots, stone rule via word-shifted above-row ch9 ballot with carries.
// block_base selects the batch-half.
// ---------------------------------------------------------------------------
__global__ void __launch_bounds__(256) k_compress(
    const float* __restrict__ world, const float* __restrict__ rnd,
    unsigned int* __restrict__ bp, int block_base)
{
    int gt   = (blockIdx.x + block_base) * 256 + threadIdx.x;
    int gw   = gt >> 5;                       // warp id, 16384 total
    int lane = gt & 31;
    int pxb  = gw << 7;                       // 128 px per warp
    int b    = pxb >> 18;
    int off  = pxb & (HW - 1);
    int h    = off >> 9;
    int ws   = off & 511;                     // 0,128,256,384
    const float* row  = world + (size_t)b * 20 * HW + (size_t)h * Wn;
    const float* rrow = rnd   + (size_t)b * HW      + (size_t)h * Wn;
    const float* p9r  = world + (size_t)b * 20 * HW + (size_t)9 * HW
                      + (size_t)(h - 1) * Wn;   // only deref when h>0

    // above-row stone masks for all 4 words + edge carries
    unsigned m9a[4];
#pragma unroll
    for (int k = 0; k < 4; k++) {
        float a = (h > 0) ? p9r[ws + 32 * k + lane] : 0.f;
        m9a[k] = __ballot_sync(~0u, a > 0.5f);
    }
    unsigned cL = 0, cR = 0;                  // uniform broadcast loads
    if (h > 0 && ws > 0)        cL = (p9r[ws - 1]   > 0.5f) ? 1u : 0u;
    if (h > 0 && ws + 128 < Wn) cR = (p9r[ws + 128] > 0.5f) ? 1u : 0u;

#pragma unroll
    for (int k = 0; k < 4; k++) {
        int w = ws + 32 * k + lane;
        int e = 0;
#pragma unroll
        for (int c = 1; c < 14; c++)
            if (row[(size_t)c * HW + w] > 0.5f) e = c;
        int den = (int)((DEN_LUT >> (3 * e)) & 7);
        int gvt = (GRV_LUT >> e) & 1;
        float r = rrow[w];

        unsigned me0 = __ballot_sync(~0u, e & 1);
        unsigned me1 = __ballot_sync(~0u, e & 2);
        unsigned me2 = __ballot_sync(~0u, e & 4);
        unsigned me3 = __ballot_sync(~0u, e & 8);
        unsigned md0 = __ballot_sync(~0u, den & 1);
        unsigned md1 = __ballot_sync(~0u, den & 2);
        unsigned md2 = __ballot_sync(~0u, den & 4);
        unsigned mg  = __ballot_sync(~0u, gvt);
        unsigned mfa = __ballot_sync(~0u, r > 0.5f);

        unsigned stone = me0 & ~me1 & ~me2 & me3;     // e == 9
        unsigned lc = k ? (m9a[k - 1] >> 31) : cL;
        unsigned rc = (k < 3) ? (m9a[k + 1] & 1u) : cR;
        unsigned L = (m9a[k] << 1) | lc;
        unsigned R = (m9a[k] >> 1) | (rc << 31);
        unsigned gv = (mg & ~stone) | (stone & ~(L & R));

        unsigned v = me0;
        v = lane == 1 ? me1 : v;  v = lane == 2 ? me2 : v;
        v = lane == 3 ? me3 : v;  v = lane == 4 ? md0 : v;
        v = lane == 5 ? md1 : v;  v = lane == 6 ? md2 : v;
        v = lane == 7 ? gv  : v;  v = lane == 8 ? mfa : v;
        if (lane < 9) bp[lane * PW + gw * 4 + k] = v;
    }
}

// ---------------------------------------------------------------------------
// Bitwise pass helpers (32 pixels per op)
// ---------------------------------------------------------------------------
__device__ __forceinline__ unsigned eq_den(const unsigned* p, int D) {
    unsigned b0 = (D & 1) ? p[4] : ~p[4];
    unsigned b1 = (D & 2) ? p[5] : ~p[5];
    unsigned b2 = (D & 4) ? p[6] : ~p[6];
    return b0 & b1 & b2;
}
__device__ __forceinline__ unsigned lt_den(const unsigned* p, int D) {
    if (D == 1) return ~p[6] & ~p[5] & ~p[4];
    if (D == 2) return ~p[6] & ~p[5];
    return ~p[6] & ~(p[5] & p[4]);              // D == 3
}
__device__ __forceinline__ unsigned gt3(
    unsigned x2, unsigned x1, unsigned x0,
    unsigned y2, unsigned y1, unsigned y0)
{
    unsigned eq2 = ~(x2 ^ y2), eq1 = ~(x1 ^ y1);
    return (x2 & ~y2) | (eq2 & x1 & ~y1) | (eq2 & eq1 & x0 & ~y0);
}

__shared__ unsigned s_mov[2][8][ITEMS];
__shared__ unsigned s_fall[ITEMS];
__shared__ unsigned s_dg[ITEMS];

template <int D>
__device__ __forceinline__ void grav_pass(
    unsigned (*src)[ITEMS], unsigned (*dst)[ITEMS], int i, int c)
{
    int rw = i * WPR + c;
    int ra = rw - WPR, rb = rw + WPR;
    unsigned s[8], a[8], bb[8];
#pragma unroll
    for (int p = 0; p < 8; p++) { s[p] = src[p][rw]; a[p] = src[p][ra]; bb[p] = src[p][rb]; }
    unsigned bel = eq_den(s, D) & lt_den(bb, D) & s[7] & bb[7];
    unsigned abv = eq_den(a, D) & lt_den(s, D) & a[7] & s[7];
    unsigned keep = ~(bel | abv);
#pragma unroll
    for (int p = 0; p < 8; p++)
        dst[p][rw] = (bel & bb[p]) | (abv & a[p]) | (keep & s[p]);
    s_dg[rw] |= abv;
}

template <int E, int LEFT>
__device__ __forceinline__ void diag_pass(
    unsigned (*src)[ITEMS], unsigned (*dst)[ITEMS], int i, int c)
{
    int rw = i * WPR + c;
    int wm = (c - 1) & 15, wp = (c + 1) & 15;
    int ba = (i - 1) * WPR, bbr = (i + 1) * WPR;

    unsigned s[8], bl[8], ar[8];
#pragma unroll
    for (int p = 0; p < 8; p++) s[p] = src[p][rw];
    unsigned sd = s_dg[rw], sf = s_fall[rw];
    unsigned bl_dg, ar_dg, ar_f;
    if (LEFT) {
#pragma unroll
        for (int p = 0; p < 8; p++) {
            bl[p] = __funnelshift_l(src[p][bbr + wm], src[p][bbr + c], 1);
            ar[p] = __funnelshift_r(src[p][ba + c], src[p][ba + wp], 1);
        }
        bl_dg = __funnelshift_l(s_dg[bbr + wm], s_dg[bbr + c], 1);
        ar_dg = __funnelshift_r(s_dg[ba + c], s_dg[ba + wp], 1);
        ar_f  = __funnelshift_r(s_fall[ba + c], s_fall[ba + wp], 1);
    } else {
#pragma unroll
        for (int p = 0; p < 8; p++) {
            bl[p] = __funnelshift_r(src[p][bbr + c], src[p][bbr + wp], 1);
            ar[p] = __funnelshift_l(src[p][ba + wm], src[p][ba + c], 1);
        }
        bl_dg = __funnelshift_r(s_dg[bbr + c], s_dg[bbr + wp], 1);
        ar_dg = __funnelshift_l(s_dg[ba + wm], s_dg[ba + c], 1);
        ar_f  = __funnelshift_l(s_fall[ba + wm], s_fall[ba + c], 1);
    }
    unsigned ms  = LEFT ? sf : ~sf;
    unsigned mar = LEFT ? ar_f : ~ar_f;
    unsigned bbl = eq_elem4(s[0], s[1], s[2], s[3], E) & ~bl_dg & ~sd & ms
                 & gt3(s[6], s[5], s[4], bl[6], bl[5], bl[4]) & s[7] & bl[7];
    unsigned bar = eq_elem4(ar[0], ar[1], ar[2], ar[3], E) & ~ar_dg & ~sd & mar
                 & gt3(ar[6], ar[5], ar[4], s[6], s[5], s[4]) & ar[7] & s[7];
    unsigned keep = ~(bbl | bar);
#pragma unroll
    for (int p = 0; p < 8; p++)
        dst[p][rw] = (bbl & bl[p]) | (bar & ar[p]) | (keep & s[p]);
}

// ---------------------------------------------------------------------------
// Fused sim (R9/R16 body) + PDL: trigger at entry (lets the next compress
// half start early), grid-dependency sync before reading g_bp.
// ---------------------------------------------------------------------------
__global__ void __launch_bounds__(NTH, 2) k_sim(
    const unsigned int* __restrict__ bp, float* __restrict__ out, int block_base)
{
#if __CUDA_ARCH__ >= 900
    if (threadIdx.x == 0) cudaTriggerProgrammaticLaunchCompletion();
    cudaGridDependencySynchronize();
#endif
    int tid = threadIdx.x;
    int bi = blockIdx.x + block_base;
    int b = bi >> 5, chunk = bi & 31;
    int r0 = chunk * TR;

    // Load 9 planes (with vertical wrap) into SMEM
#pragma unroll
    for (int p = 0; p < 9; p++) {
        const unsigned* pp = bp + (size_t)p * PW + (size_t)b * (Hn * WPR);
        for (int rw = tid; rw < ITEMS; rw += NTH) {
            int i = rw >> 4, wq = rw & 15;
            int gr = (r0 - HALO + i) & (Hn - 1);
            unsigned v = pp[gr * WPR + wq];
            if (p < 8) s_mov[0][p][rw] = v; else s_fall[rw] = v;
        }
    }
    for (int rw = tid; rw < ITEMS; rw += NTH) s_dg[rw] = 0;
    __syncthreads();

    // Pass k computes exactly rows [k, RT-k)
    int i = (tid >> 4), c = tid & 15;
    if (tid < (RT- 2)*WPR) grav_pass<1>(s_mov[0], s_mov[1], i + 1, c);    __syncthreads();
    if (tid < (RT- 4)*WPR) grav_pass<2>(s_mov[1], s_mov[0], i + 2, c);    __syncthreads();
    if (tid < (RT- 6)*WPR) grav_pass<3>(s_mov[0], s_mov[1], i + 3, c);    __syncthreads();
    if (tid < (RT- 8)*WPR) diag_pass<2 ,1>(s_mov[1], s_mov[0], i + 4, c); __syncthreads();
    if (tid < (RT-10)*WPR) diag_pass<2 ,0>(s_mov[0], s_mov[1], i + 5, c); __syncthreads();
    if (tid < (RT-12)*WPR) diag_pass<12,1>(s_mov[1], s_mov[0], i + 6, c); __syncthreads();
    if (tid < (RT-14)*WPR) diag_pass<12,0>(s_mov[0], s_mov[1], i + 7, c); __syncthreads();
    // final state in s_mov[1], valid rows [HALO, HALO+TR)

    // Decompress valid rows to the 20-channel f32 world
    float* ob = out + (size_t)b * 20 * HW;
    for (int g2 = tid; g2 < TR * 128; g2 += NTH) {
        int ii = (g2 >> 7) + HALO;
        int q  = g2 & 127;                 // float4 group within row
        int wq = q >> 3;
        int k  = (q & 7) * 4;
        int rw = ii * WPR + wq;
        unsigned p0 = s_mov[1][0][rw], p1 = s_mov[1][1][rw];
        unsigned p2 = s_mov[1][2][rw], p3 = s_mov[1][3][rw];
        unsigned p4 = s_mov[1][4][rw], p5 = s_mov[1][5][rw];
        unsigned p6 = s_mov[1][6][rw], p7 = s_mov[1][7][rw];
        int e[4]; float dn[4], gv[4];
#pragma unroll
        for (int j = 0; j < 4; j++) {
            int kk = k + j;
            e[j] = ((p0 >> kk) & 1) | (((p1 >> kk) & 1) << 1)
                 | (((p2 >> kk) & 1) << 2) | (((p3 >> kk) & 1) << 3);
            dn[j] = (float)(((p4 >> kk) & 1) | (((p5 >> kk) & 1) << 1)
                          | (((p6 >> kk) & 1) << 2));
            gv[j] = (float)((p7 >> kk) & 1);
        }
        int gh = r0 + ii - HALO;
        float* op = ob + (size_t)gh * Wn + q * 4;
#pragma unroll
        for (int ch = 0; ch < 14; ch++) {
            float4 v = make_float4(e[0] == ch ? 1.f : 0.f, e[1] == ch ? 1.f : 0.f,
                                   e[2] == ch ? 1.f : 0.f, e[3] == ch ? 1.f : 0.f);
            *reinterpret_cast<float4*>(op + (size_t)ch * HW) = v;
        }
        *reinterpret_cast<float4*>(op + (size_t)14 * HW) =
            make_float4(dn[0], dn[1], dn[2], dn[3]);
        *reinterpret_cast<float4*>(op + (size_t)15 * HW) =
            make_float4(gv[0], gv[1], gv[2], gv[3]);
        float4 z = make_float4(0.f, 0.f, 0.f, 0.f);
#pragma unroll
        for (int ch = 16; ch < 20; ch++)
            *reinterpret_cast<float4*>(op + (size_t)ch * HW) = z;
    }
}

// ---------------------------------------------------------------------------
// Launch: c0 -> s0 -> c1 -> s1 with PDL so c1 overlaps s0 (read-stream
// overlapping write-stream). Falls back to serialized order if PDL inactive.
// ---------------------------------------------------------------------------
extern "C" void kernel_launch(void* const* d_in, const int* in_sizes, int n_in,
                              void* d_out, int out_size)
{
    int wi = 0, ri = 1;
    if (n_in >= 2 && in_sizes[0] < in_sizes[1]) { wi = 1; ri = 0; }
    const float* world = (const float*)d_in[wi];
    const float* rnd   = (const float*)d_in[ri];
    float* out = (float*)d_out;

    unsigned int* bp;
    cudaGetSymbolAddress((void**)&bp, g_bp);

    const int CH = CBLK / 2;   // 1024 compress blocks per half
    const int SH = NBLK / 2;   // 128 sim blocks per half

    cudaLaunchAttribute attr[1];
    attr[0].id = cudaLaunchAttributeProgrammaticStreamSerialization;
    attr[0].val.programmaticStreamSerializationAllowed = 1;

    // c0: plain launch (half 0 = batches 0..3)
    k_compress<<<CH, 256>>>(world, rnd, bp, 0);

    // s0: PDL launch; triggers at entry so c1 can start while s0 runs,
    // gridsync waits for c0 completion before reading g_bp.
    {
        cudaLaunchConfig_t cfg = {};
        cfg.gridDim = dim3(SH); cfg.blockDim = dim3(NTH);
        cfg.attrs = attr; cfg.numAttrs = 1;
        cudaLaunchKernelEx(&cfg, k_sim, (const unsigned int*)bp, out, 0);
    }
    // c1: PDL launch; starts when s0 triggers (i.e. immediately after s0
    // begins). Writes g_bp half 1 — disjoint from s0's reads of half 0.
    {
        cudaLaunchConfig_t cfg = {};
        cfg.gridDim = dim3(CH); cfg.blockDim = dim3(256);
        cfg.attrs = attr; cfg.numAttrs = 1;
        cudaLaunchKernelEx(&cfg, k_compress, world, rnd, (unsigned int*)bp, CH);
    }
    // s1: PDL launch; gridsync waits for c1 completion before reading g_bp.
    {
        cudaLaunchConfig_t cfg = {};
        cfg.gridDim = dim3(SH); cfg.blockDim = dim3(NTH);
        cfg.attrs = attr; cfg.numAttrs = 1;
        cudaLaunchKernelEx(&cfg, k_sim, (const unsigned int*)bp, out, SH);
    }
}